// round 3
// baseline (speedup 1.0000x reference)
#include <cuda_runtime.h>
#include <cstddef>

// CapsuleLayer dynamic routing, fully fp32, recompute-u_hat strategy.
// Shapes: B=64, IN_CAPS=2048, IN_DIM=8, OUT_CAPS=32, OUT_DIM=16, 3 routing iters.

#define GX    128   // i-chunks per pass; GX * IPER == IC
#define IPER  16
#define NB    64    // batch
#define IC    2048
#define OC    32
#define OD    16
#define IDIM  8
#define BGSZ  32    // batches handled per CTA (2 groups)

// Scratch (static device allocations are the sanctioned workaround)
__device__ float g_P[2 * GX * BGSZ * OD * OC];   // partial s: [bg][x][bl][j][o]  (16 MB)
__device__ float g_v[NB * OD * OC];              // v: [b][j][o]
__device__ float g_bmat[(size_t)NB * IC * OC];   // routing logits b_ij: [b][i][o] (16.8 MB)

// ---------------------------------------------------------------------------
// Pass kernel: for each capsule i in this CTA's chunk, recompute
// u_hat[b,i,o,j] = sum_d W[i,o,j,d] * x[b,i,d]   (W held in registers, lane=o)
// then apply routing weights and accumulate s partial sums in SMEM.
// ITER 0: c = 1/32 (softmax of zeros). ITER 1: b = u.v0, write bmat.
// ITER 2: b = bmat + u.v1.
// ---------------------------------------------------------------------------
template <int ITER>
__global__ __launch_bounds__(256, 1)
void caps_pass(const float* __restrict__ xg, const float* __restrict__ Wg) {
    extern __shared__ float smem[];
    float* s_sh = smem;             // [BGSZ][OD][OC] = 16384 floats
    float* v_sh = smem + 16384;     // [BGSZ][OD][OC] = 16384 floats
    float* Wsh  = smem + 32768;     // [128][33]      = 4224 floats (padded, conflict-free)
    float* xs   = smem + 36992;     // [BGSZ][IDIM]   = 256 floats

    const int t    = threadIdx.x;
    const int lane = t & 31;        // lane == output capsule o
    const int w    = t >> 5;        // warp id 0..7
    const int bg   = blockIdx.y;    // batch group (0 or 1)
    const int b_base = bg * BGSZ;

    // zero the s accumulator
    #pragma unroll
    for (int k = 0; k < 64; ++k) s_sh[t + k * 256] = 0.0f;

    // load v from previous iteration (layout [b][j][o], contiguous slice)
    if (ITER >= 1) {
        const float4* src = (const float4*)(g_v + b_base * (OD * OC));
        float4* dst = (float4*)v_sh;
        #pragma unroll
        for (int k = 0; k < 16; ++k) dst[t + k * 256] = src[t + k * 256];
    }

    const int i0 = blockIdx.x * IPER;

    for (int ic = 0; ic < IPER; ++ic) {
        const int i = i0 + ic;
        __syncthreads();  // previous iteration done with Wsh/xs; v_sh ready (first iter)

        // stage W[i] (4096 floats) transposed into [jd][o] with +1 padding
        {
            const float* wsrc = Wg + (size_t)i * (OC * OD * IDIM);
            #pragma unroll
            for (int k = 0; k < 16; ++k) {
                int e = t + k * 256;          // e = o*128 + (j*8+d)
                float val = wsrc[e];
                int o  = e >> 7;
                int jd = e & 127;
                Wsh[jd * 33 + o] = val;
            }
            // stage x[b_base..b_base+32)[i][0..8)
            int bl = t >> 3, d = t & 7;
            xs[t] = xg[(size_t)(b_base + bl) * (IC * IDIM) + i * IDIM + d];
        }
        __syncthreads();

        // W[i, o=lane, :, :] into registers (conflict-free column reads)
        float Wr[128];
        #pragma unroll
        for (int jd = 0; jd < 128; ++jd) Wr[jd] = Wsh[jd * 33 + lane];

        #pragma unroll 1   // keep register pressure bounded (Wr=128 regs live)
        for (int bb = 0; bb < 4; ++bb) {
            const int bl = w * 4 + bb;

            float xr[8];
            #pragma unroll
            for (int d = 0; d < 8; ++d) xr[d] = xs[bl * 8 + d];

            // u_hat[b,i,o=lane,j] for j=0..15
            float u[16];
            #pragma unroll
            for (int j = 0; j < 16; ++j) {
                float acc = Wr[j * 8] * xr[0];
                #pragma unroll
                for (int d = 1; d < 8; ++d) acc = fmaf(Wr[j * 8 + d], xr[d], acc);
                u[j] = acc;
            }

            float c;
            if (ITER == 0) {
                c = 1.0f / 32.0f;  // softmax of zeros over 32 capsules
            } else {
                // agreement a = sum_j u[j] * v[b, o=lane, j]
                float a = 0.0f;
                #pragma unroll
                for (int j = 0; j < 16; ++j)
                    a = fmaf(u[j], v_sh[(bl * 16 + j) * 32 + lane], a);

                const size_t bidx = ((size_t)(b_base + bl) * IC + i) * OC + lane;
                float logit = a;
                if (ITER == 2) logit += g_bmat[bidx];
                if (ITER == 1) g_bmat[bidx] = a;

                // softmax over o (= lanes of this warp)
                float m = logit;
                #pragma unroll
                for (int d = 16; d >= 1; d >>= 1)
                    m = fmaxf(m, __shfl_xor_sync(0xffffffffu, m, d));
                float e = __expf(logit - m);
                float ssum = e;
                #pragma unroll
                for (int d = 16; d >= 1; d >>= 1)
                    ssum += __shfl_xor_sync(0xffffffffu, ssum, d);
                c = e / ssum;
            }

            // s_part[b][j][o] += c * u[j]  (lane=o -> conflict-free banks)
            #pragma unroll
            for (int j = 0; j < 16; ++j) {
                int idx = (bl * 16 + j) * 32 + lane;
                s_sh[idx] += c * u[j];
            }
        }
    }

    __syncthreads();
    // flush partials (coalesced)
    float* pdst = g_P + ((size_t)(bg * GX) + blockIdx.x) * (BGSZ * OD * OC);
    #pragma unroll
    for (int k = 0; k < 64; ++k) pdst[t + k * 256] = s_sh[t + k * 256];
}

// ---------------------------------------------------------------------------
// Reduce partials over i-chunks, squash, emit v (or final output on iter 2).
// grid 64 (b), block 512 (t = j*32 + o)
// ---------------------------------------------------------------------------
__global__ void reduce_squash(int iter, float* __restrict__ out) {
    const int b  = blockIdx.x;
    const int t  = threadIdx.x;       // t = j*32 + o
    const int bg = b >> 5;
    const int bl = b & 31;
    const int o  = t & 31;
    const int j  = t >> 5;

    float s = 0.0f;
    const float* base = g_P + (size_t)(bg * GX) * (BGSZ * OD * OC) + bl * (OD * OC) + t;
    #pragma unroll 4
    for (int x = 0; x < GX; ++x) s += base[(size_t)x * (BGSZ * OD * OC)];

    __shared__ float red[512];
    red[t] = s * s;
    __syncthreads();
    #pragma unroll
    for (int st = 8; st >= 1; st >>= 1) {
        if (j < st) red[t] += red[t + st * 32];
        __syncthreads();
    }
    const float s2 = red[o];  // sum_j s^2 for this (b,o)
    const float scale = (s2 / (1.0f + s2)) * rsqrtf(s2 + 1e-9f);
    const float v = s * scale;

    if (iter < 2)
        g_v[b * (OD * OC) + t] = v;          // [b][j][o]
    else
        out[(b * OC + o) * OD + j] = v;      // output layout [b][o][j]
}

// ---------------------------------------------------------------------------
extern "C" void kernel_launch(void* const* d_in, const int* in_sizes, int n_in,
                              void* d_out, int out_size) {
    (void)n_in; (void)out_size;
    const float* x = (const float*)d_in[0];
    const float* W = (const float*)d_in[1];
    if (in_sizes[0] > in_sizes[1]) {  // defensive: x has 1M elems, W has 8.4M
        const float* tmp = x; x = W; W = tmp;
    }
    float* out = (float*)d_out;

    const size_t smem_bytes = 37248 * sizeof(float);  // ~149 KB
    cudaFuncSetAttribute(caps_pass<0>, cudaFuncAttributeMaxDynamicSharedMemorySize, (int)smem_bytes);
    cudaFuncSetAttribute(caps_pass<1>, cudaFuncAttributeMaxDynamicSharedMemorySize, (int)smem_bytes);
    cudaFuncSetAttribute(caps_pass<2>, cudaFuncAttributeMaxDynamicSharedMemorySize, (int)smem_bytes);

    dim3 grid(GX, 2);
    caps_pass<0><<<grid, 256, smem_bytes>>>(x, W);
    reduce_squash<<<64, 512>>>(0, out);
    caps_pass<1><<<grid, 256, smem_bytes>>>(x, W);
    reduce_squash<<<64, 512>>>(1, out);
    caps_pass<2><<<grid, 256, smem_bytes>>>(x, W);
    reduce_squash<<<64, 512>>>(2, out);
}

// round 4
// speedup vs baseline: 1.3906x; 1.3906x over previous
#include <cuda_runtime.h>
#include <cstdint>
#include <cstddef>

// CapsuleLayer dynamic routing — fp32 with f32x2 packed FMA, recompute-u_hat.
// B=64, IN_CAPS=2048, IN_DIM=8, OUT_CAPS=32, OUT_DIM=16, 3 routing iters.

#define NB   64
#define IC   2048
#define OC   32
#define OD   16
#define IDIM 8
#define IPER 16
#define GX   (IC / IPER)   // 128
#define BGSZ 32

typedef unsigned long long ull;

// Scratch (__device__ globals are the sanctioned scratch mechanism)
__device__ float g_s[NB * OC * OD];              // [b][o][j] atomic accumulators (zeroed by squash)
__device__ float g_v[NB * (OD / 2) * OC * 2];    // [b][p][o] float2 = (v[2p], v[2p+1])
__device__ float g_bmat[(size_t)NB * IC * OC];   // routing logits from iter 1

// ---- f32x2 helpers -------------------------------------------------------
__device__ __forceinline__ ull ffma2(ull a, ull b, ull c) {
    ull d;
    asm("fma.rn.f32x2 %0, %1, %2, %3;" : "=l"(d) : "l"(a), "l"(b), "l"(c));
    return d;
}
__device__ __forceinline__ ull fdup(float x) {
    ull d;
    asm("mov.b64 %0, {%1, %1};" : "=l"(d) : "f"(x));
    return d;
}
__device__ __forceinline__ float flo(ull v) { return __uint_as_float((unsigned)v); }
__device__ __forceinline__ float fhi(ull v) { return __uint_as_float((unsigned)(v >> 32)); }

__device__ __forceinline__ void red4(float* p, float a, float b, float c, float d) {
    asm volatile("red.global.add.v4.f32 [%0], {%1, %2, %3, %4};"
                 :: "l"(p), "f"(a), "f"(b), "f"(c), "f"(d) : "memory");
}

// SMEM layout (in ull units):
//   Wsh : [32 o][66] float2-slots  -> 2112 ull  (element (o,d,p) at o*66+d*8+p = (W[o][2p][d], W[o][2p+1][d]))
//   vsh : [32 bl][8 p][32 o] ull   -> 8192 ull  (only ITER>=1)
//   xsh : [32 bl][16 ic][8 d] f32  -> 2048 ull-equiv
#define WSH_ULL 2112
#define VSH_ULL 8192
#define SMEM_BYTES ((WSH_ULL + VSH_ULL) * 8 + BGSZ * IPER * IDIM * 4)

template <int ITER>
__global__ __launch_bounds__(256, 1)
void caps_pass(const float* __restrict__ xg, const float* __restrict__ Wg) {
    extern __shared__ ull smem_u[];
    ull*   Wsh = smem_u;
    ull*   vsh = smem_u + WSH_ULL;
    float* xsh = (float*)(smem_u + WSH_ULL + VSH_ULL);

    const int t      = threadIdx.x;
    const int lane   = t & 31;            // lane == output capsule o
    const int w      = t >> 5;            // warp 0..7; warp handles b-rows w*4..w*4+3
    const int bg     = blockIdx.y;
    const int b_base = bg * BGSZ;
    const int i0     = blockIdx.x * IPER;

    // Stage v (constant for the whole pass): g_v slice is contiguous [bl][p][o]
    if (ITER >= 1) {
        const ull* vg = ((const ull*)g_v) + (size_t)b_base * 8 * 32;
        #pragma unroll
        for (int k = 0; k < 32; ++k) vsh[t + k * 256] = vg[t + k * 256];
    }

    // Stage x for the whole i-chunk: per bl, 128 contiguous floats
    {
        const int bl = t >> 3;
        const int c8 = t & 7;
        const float4* src = (const float4*)(xg + (size_t)(b_base + bl) * (IC * IDIM) + i0 * IDIM);
        float4* dst = (float4*)(xsh + bl * 128);
        #pragma unroll
        for (int c = 0; c < 4; ++c) dst[c8 * 4 + c] = src[c8 * 4 + c];
    }

    // Prefetch W for first i into registers (thread owns o=lane, j in {2w,2w+1}, d 0..7)
    float4 wreg[4];
    {
        const float4* wsrc = (const float4*)(Wg + (size_t)i0 * (OC * OD * IDIM) + lane * 128 + w * 16);
        #pragma unroll
        for (int c = 0; c < 4; ++c) wreg[c] = wsrc[c];
    }

    // j-packed s accumulators: s2[bb][p] = (s[j=2p], s[j=2p+1])
    ull s2[4][8];
    #pragma unroll
    for (int bb = 0; bb < 4; ++bb)
        #pragma unroll
        for (int p = 0; p < 8; ++p) s2[bb][p] = 0ULL;

    for (int ic = 0; ic < IPER; ++ic) {
        const int i = i0 + ic;

        __syncthreads();  // previous iteration's readers done with Wsh

        // STS staged W in paired (o,d,p) layout
        {
            const float* wf = (const float*)wreg;   // wf[0..7]=j=2w d0..7, wf[8..15]=j=2w+1
            #pragma unroll
            for (int d = 0; d < 8; ++d)
                ((float2*)Wsh)[lane * 66 + d * 8 + w] = make_float2(wf[d], wf[8 + d]);
        }
        __syncthreads();

        // Prefetch next i's W (hides DRAM/L2 latency behind compute)
        if (ic + 1 < IPER) {
            const float4* wsrc = (const float4*)(Wg + (size_t)(i + 1) * (OC * OD * IDIM) + lane * 128 + w * 16);
            #pragma unroll
            for (int c = 0; c < 4; ++c) wreg[c] = wsrc[c];
        }

        // Prefetch routing logits for ITER 2
        float bm[4];
        if (ITER == 2) {
            #pragma unroll
            for (int bb = 0; bb < 4; ++bb)
                bm[bb] = g_bmat[((size_t)(b_base + w * 4 + bb) * IC + i) * OC + lane];
        }

        // x into registers (warp-uniform broadcast reads)
        float xr[4][8];
        #pragma unroll
        for (int bb = 0; bb < 4; ++bb) {
            const float4* xp = (const float4*)(xsh + (w * 4 + bb) * 128 + ic * 8);
            float4 x0 = xp[0], x1 = xp[1];
            xr[bb][0] = x0.x; xr[bb][1] = x0.y; xr[bb][2] = x0.z; xr[bb][3] = x0.w;
            xr[bb][4] = x1.x; xr[bb][5] = x1.y; xr[bb][6] = x1.z; xr[bb][7] = x1.w;
        }

        // Core: u2[bb][p] = (u[2p], u[2p+1]) accumulated over d.
        // ITER 0 folds the constant c=1/32 and accumulates straight into s2.
        ull u2[4][8];
        if (ITER >= 1) {
            #pragma unroll
            for (int bb = 0; bb < 4; ++bb)
                #pragma unroll
                for (int p = 0; p < 8; ++p) u2[bb][p] = 0ULL;
        }

        #pragma unroll
        for (int d = 0; d < 8; ++d) {
            const ulonglong2* wrow = (const ulonglong2*)(Wsh + lane * 66 + d * 8);
            ulonglong2 wa = wrow[0], wb = wrow[1], wc = wrow[2], wd = wrow[3];
            ull wv0 = wa.x, wv1 = wa.y, wv2 = wb.x, wv3 = wb.y;
            ull wv4 = wc.x, wv5 = wc.y, wv6 = wd.x, wv7 = wd.y;
            #pragma unroll
            for (int bb = 0; bb < 4; ++bb) {
                ull xd = fdup(xr[bb][d]);
                ull* acc = (ITER == 0) ? s2[bb] : u2[bb];
                acc[0] = ffma2(wv0, xd, acc[0]);
                acc[1] = ffma2(wv1, xd, acc[1]);
                acc[2] = ffma2(wv2, xd, acc[2]);
                acc[3] = ffma2(wv3, xd, acc[3]);
                acc[4] = ffma2(wv4, xd, acc[4]);
                acc[5] = ffma2(wv5, xd, acc[5]);
                acc[6] = ffma2(wv6, xd, acc[6]);
                acc[7] = ffma2(wv7, xd, acc[7]);
            }
        }

        if (ITER >= 1) {
            #pragma unroll
            for (int bb = 0; bb < 4; ++bb) {
                const int bl = w * 4 + bb;

                // agreement a = sum_j u[j]*v[j]  (packed, then horizontal add)
                ull a2 = 0ULL;
                #pragma unroll
                for (int p = 0; p < 8; ++p)
                    a2 = ffma2(u2[bb][p], vsh[(bl * 8 + p) * 32 + lane], a2);
                float a = flo(a2) + fhi(a2);

                if (ITER == 2) a += bm[bb];
                if (ITER == 1)
                    g_bmat[((size_t)(b_base + bl) * IC + i) * OC + lane] = a;

                // softmax over o (= lanes). |a| << 1, no max-subtraction needed.
                float e = __expf(a);
                float ssum = e;
                #pragma unroll
                for (int dd = 16; dd >= 1; dd >>= 1)
                    ssum += __shfl_xor_sync(0xffffffffu, ssum, dd);
                ull c2 = fdup(e / ssum);

                #pragma unroll
                for (int p = 0; p < 8; ++p)
                    s2[bb][p] = ffma2(c2, u2[bb][p], s2[bb][p]);
            }
        }
    }

    // Flush register accumulators via vector reductions into g_s[b][o][j]
    const float scale = (ITER == 0) ? (1.0f / 32.0f) : 1.0f;
    #pragma unroll
    for (int bb = 0; bb < 4; ++bb) {
        const int b = b_base + w * 4 + bb;
        float* dst = g_s + ((size_t)b * OC + lane) * OD;
        #pragma unroll
        for (int k = 0; k < 4; ++k) {
            float f0 = flo(s2[bb][2 * k])     * scale;
            float f1 = fhi(s2[bb][2 * k])     * scale;
            float f2 = flo(s2[bb][2 * k + 1]) * scale;
            float f3 = fhi(s2[bb][2 * k + 1]) * scale;
            red4(dst + 4 * k, f0, f1, f2, f3);
        }
    }
}

// ---------------------------------------------------------------------------
// Squash: read g_s[b][o][j], reduce over j, squash, emit v (or final output).
// Also re-zeros g_s so the next pass (and the next graph replay) starts clean.
// grid 64 (b), block 512 (t = o*16 + j)
// ---------------------------------------------------------------------------
__global__ void squash_k(int iter, float* __restrict__ out) {
    const int b = blockIdx.x;
    const int t = threadIdx.x;
    const int o = t >> 4;
    const int j = t & 15;
    const int idx = (b * OC + o) * OD + j;

    const float s = g_s[idx];
    float sq = s * s;
    #pragma unroll
    for (int d = 8; d >= 1; d >>= 1)
        sq += __shfl_xor_sync(0xffffffffu, sq, d);   // 16-lane groups share o

    const float scale = (sq / (1.0f + sq)) * rsqrtf(sq + 1e-9f);
    const float v = s * scale;

    if (iter < 2)
        g_v[((b * 8 + (j >> 1)) * 32 + o) * 2 + (j & 1)] = v;  // [b][p][o] float2 layout
    else
        out[idx] = v;                                           // [b][o][j]

    g_s[idx] = 0.0f;  // ready for next pass / next replay
}

// ---------------------------------------------------------------------------
extern "C" void kernel_launch(void* const* d_in, const int* in_sizes, int n_in,
                              void* d_out, int out_size) {
    (void)n_in; (void)out_size;
    const float* x = (const float*)d_in[0];
    const float* W = (const float*)d_in[1];
    if (in_sizes[0] > in_sizes[1]) {  // defensive: x=1M elems, W=8.4M elems
        const float* tmp = x; x = W; W = tmp;
    }
    float* out = (float*)d_out;

    cudaFuncSetAttribute(caps_pass<0>, cudaFuncAttributeMaxDynamicSharedMemorySize, SMEM_BYTES);
    cudaFuncSetAttribute(caps_pass<1>, cudaFuncAttributeMaxDynamicSharedMemorySize, SMEM_BYTES);
    cudaFuncSetAttribute(caps_pass<2>, cudaFuncAttributeMaxDynamicSharedMemorySize, SMEM_BYTES);

    dim3 grid(GX, 2);
    caps_pass<0><<<grid, 256, SMEM_BYTES>>>(x, W);
    squash_k<<<64, 512>>>(0, out);
    caps_pass<1><<<grid, 256, SMEM_BYTES>>>(x, W);
    squash_k<<<64, 512>>>(1, out);
    caps_pass<2><<<grid, 256, SMEM_BYTES>>>(x, W);
    squash_k<<<64, 512>>>(2, out);
}